// round 16
// baseline (speedup 1.0000x reference)
#include <cuda_runtime.h>
#include <cuda_bf16.h>
#include <stdint.h>
#include <math.h>

typedef unsigned int u32;
typedef unsigned short u16;

// Fixed problem shape
#define NROWS 8192
#define DIM   128
#define BCLS  64
#define RBLK  128
#define NRB   64
#define NTILE_TOT 2080
#define NBLK  128
#define NTHR  512
#define TILEB 16384        // fp8 tile: 128 rows x 128B

__device__ __align__(256) unsigned char g_feat8[NROWS * DIM];   // normalized e4m3
__device__ float g_rowA[NRB][4][4][RBLK];     // [rowblk][sub][cg][row]
__device__ float g_rowP[NRB][4][4][RBLK];
__device__ float g_tcA[NTILE_TOT][4][RBLK];   // col-side, per rg
__device__ float g_tcP[NTILE_TOT][4][RBLK];
__device__ float g_partial[NRB];
__device__ int g_ctr;

__device__ __forceinline__ int tri(int I) { return I * 64 - ((I * (I - 1)) >> 1); }

// ---------------------------------------------------------------------------
// PTX helpers
// ---------------------------------------------------------------------------
__device__ __forceinline__ u32 smem_u32(const void* p) {
    return (u32)__cvta_generic_to_shared(p);
}
__device__ __forceinline__ void cp16(u32 dst, const void* src) {
    asm volatile("cp.async.cg.shared.global [%0], [%1], 16;\n" :: "r"(dst), "l"(src));
}
__device__ __forceinline__ void cp_commit() {
    asm volatile("cp.async.commit_group;\n" ::: "memory");
}
template <int N>
__device__ __forceinline__ void cp_wait() {
    asm volatile("cp.async.wait_group %0;\n" :: "n"(N) : "memory");
}
__device__ __forceinline__ void ldsm4(u32& q0, u32& q1, u32& q2, u32& q3, u32 addr) {
    asm volatile("ldmatrix.sync.aligned.m8n8.x4.shared.b16 {%0,%1,%2,%3}, [%4];"
                 : "=r"(q0), "=r"(q1), "=r"(q2), "=r"(q3) : "r"(addr));
}
__device__ __forceinline__ void mma_fp8(float* dacc, u32 qa0, u32 qa1, u32 qa2, u32 qa3,
                                        u32 qb0, u32 qb1) {
    asm volatile("mma.sync.aligned.m16n8k32.row.col.f32.e4m3.e4m3.f32 "
                 "{%0,%1,%2,%3}, {%4,%5,%6,%7}, {%8,%9}, {%0,%1,%2,%3};"
                 : "+f"(dacc[0]), "+f"(dacc[1]), "+f"(dacc[2]), "+f"(dacc[3])
                 : "r"(qa0), "r"(qa1), "r"(qa2), "r"(qa3), "r"(qb0), "r"(qb1));
}
__device__ __forceinline__ float ex2f(float v) {
    float r;
    asm("ex2.approx.f32 %0, %1;" : "=f"(r) : "f"(v));
    return r;
}

// Re-entrant grid barrier (all NBLK blocks co-resident).
__device__ __forceinline__ void grid_barrier() {
    __syncthreads();
    if (threadIdx.x == 0) {
        __threadfence();
        int t = atomicAdd(&g_ctr, 1);
        int target = (t / NBLK + 1) * NBLK;
        while (atomicAdd(&g_ctr, 0) < target) { __nanosleep(64); }
        __threadfence();
    }
    __syncthreads();
}

// fp8 tile loader: 128 rows x 128B -> smem, XOR-16B swizzle within 128B row.
// 1024 chunks, 512 threads -> 2 each.
__device__ __forceinline__ void load_tile8(u32 sbase,
                                           const unsigned char* gbase, int tid) {
    #pragma unroll
    for (int i = 0; i < 2; i++) {
        int id = i * NTHR + tid;
        int r  = id >> 3;
        int c  = id & 7;
        u32 dst = sbase + r * 128 + ((c ^ (r & 7)) << 4);
        cp16(dst, gbase + r * 128 + c * 16);
    }
}

// ---------------------------------------------------------------------------
// ONE persistent kernel, strip-decomposed symmetric tiles, fp8 e4m3 MMA.
// Pair p = b>>2: rows I1=p (64-p tiles) + I2=63-p (p+1 tiles) = 65 tiles.
// Block sub = b&3 takes 17/16/16/16 tiles. B bufs by local idx parity.
// ---------------------------------------------------------------------------
__global__ __launch_bounds__(NTHR) void mono_strip8_kernel(const float* __restrict__ x,
                                                           const int* __restrict__ y,
                                                           float* __restrict__ out) {
    extern __shared__ __align__(1024) char smem[];
    __shared__ int ysm[BCLS];
    __shared__ float red[RBLK];

    const int tid  = threadIdx.x;
    const int lane = tid & 31;
    const int w    = tid >> 5;
    const int b    = blockIdx.x;

    // ---------------- Phase 1: normalize 64 rows -> e4m3, zero row scratch -
    #pragma unroll
    for (int i = 0; i < 4; i++) {
        int row = b * 64 + w * 4 + i;
        float4 v = ((const float4*)(x + (size_t)row * DIM))[lane];
        float ss = v.x * v.x + v.y * v.y + v.z * v.z + v.w * v.w;
        #pragma unroll
        for (int o = 16; o; o >>= 1) ss += __shfl_xor_sync(0xffffffffu, ss, o);
        float inv = 1.0f / fmaxf(sqrtf(ss), 1e-12f);
        u16 p01, p23;
        asm("cvt.rn.satfinite.e4m3x2.f32 %0, %1, %2;" : "=h"(p01)
            : "f"(v.y * inv), "f"(v.x * inv));
        asm("cvt.rn.satfinite.e4m3x2.f32 %0, %1, %2;" : "=h"(p23)
            : "f"(v.w * inv), "f"(v.z * inv));
        ((u32*)(g_feat8 + (size_t)row * DIM))[lane] = (u32)p01 | ((u32)p23 << 16);
    }
    {   // zero g_rowA/g_rowP: 131072 floats each -> 1024 per block per array
        float* za = &g_rowA[0][0][0][0];
        float* zp = &g_rowP[0][0][0][0];
        za[b * 1024 + tid]       = 0.f;
        za[b * 1024 + 512 + tid] = 0.f;
        zp[b * 1024 + tid]       = 0.f;
        zp[b * 1024 + 512 + tid] = 0.f;
    }
    if (tid < BCLS) ysm[tid] = y[tid];

    grid_barrier();

    // ---------------- Phase 2: strip mainloop (fp8) ------------------------
    const u32 sA  = smem_u32(smem);
    const u32 sB0 = sA + TILEB;
    const u32 sB1 = sA + 2 * TILEB;
    const int rg = w >> 2, cg = w & 3;
    const int l3 = lane & 3, lq = lane >> 2;

    const int p   = b >> 2;
    const int sub = b & 3;
    const int I2s = 63 - p;
    const int n1 = 64 - p;
    const int k0 = (sub == 0) ? 0 : sub * 16 + 1;
    const int k1 = k0 + ((sub == 0) ? 17 : 16);

    #define K_I(k) ((k) < n1 ? p : I2s)
    #define K_J(k) ((k) < n1 ? p + (k) : I2s + ((k) - n1))

    // prologue: A(segment start) + B(k0) -> buf0 (one group)
    load_tile8(sA,  g_feat8 + (size_t)K_I(k0) * RBLK * DIM, tid);
    load_tile8(sB0, g_feat8 + (size_t)K_J(k0) * RBLK * DIM, tid);
    cp_commit();

    // ldsm addressing (fp8, 128B rows)
    const int lrow = lane & 15;
    const u32 hi   = (u32)(lane >> 4);
    const u32 sw   = (u32)(lrow & 7);
    const u32 QA0 = sA + (u32)((rg * 32 + lrow) * 128);          // m-half 0
    const u32 QA1 = QA0 + 2048;                                   // +16 rows
    const u32 cBo = (u32)((cg * 32 + lrow) * 128);

    const float L2E = 1.4426950408889634f;
    float ra[2][2] = {{0.f,0.f},{0.f,0.f}}, rp[2][2] = {{0.f,0.f},{0.f,0.f}};

    int idx = 0;
    for (int t = k0; t < k1; t++, idx++) {
        if (t == n1 && t > k0) {
            load_tile8(sA, g_feat8 + (size_t)I2s * RBLK * DIM, tid);
            if (t + 1 < k1)
                load_tile8((idx & 1) ? sB0 : sB1,
                           g_feat8 + (size_t)K_J(t + 1) * RBLK * DIM, tid);
            cp_commit();
            cp_wait<0>();
        } else if (t + 1 < k1) {
            load_tile8((idx & 1) ? sB0 : sB1,
                       g_feat8 + (size_t)K_J(t + 1) * RBLK * DIM, tid);
            cp_commit();
            cp_wait<1>();
        } else {
            cp_wait<0>();
        }
        __syncthreads();

        const int I = K_I(t);
        const int J = K_J(t);
        const int nt = tri(I) + (J - I);
        const int clsI = ysm[I];
        const int clsJ = ysm[J];
        const bool diag = (I == J);

        // masks
        float mf[4][2];
        #pragma unroll
        for (int n = 0; n < 4; n++) {
            int c0 = (cg & 1) * 32 + n * 8 + 2 * l3;
            mf[n][0] = (ysm[c0]     == clsI) ? 1.0f : 0.0f;
            mf[n][1] = (ysm[c0 + 1] == clsI) ? 1.0f : 0.0f;
        }
        float mc[2][2];
        #pragma unroll
        for (int m = 0; m < 2; m++) {
            #pragma unroll
            for (int h = 0; h < 2; h++)
                mc[m][h] = (clsJ == ysm[(rg & 1) * 32 + m * 16 + h * 8 + lq]) ? 1.0f : 0.0f;
        }

        // MMA: fp8 k32, 4 s-steps
        float acc[2][4][4];
        #pragma unroll
        for (int m = 0; m < 2; m++)
            #pragma unroll
            for (int n = 0; n < 4; n++)
                #pragma unroll
                for (int q = 0; q < 4; q++) acc[m][n][q] = 0.f;

        const u32 B0 = ((idx & 1) ? sB1 : sB0) + cBo;
        const u32 B1 = B0 + 2048;

        #pragma unroll
        for (int s = 0; s < 4; s++) {
            const u32 ch  = (u32)(2 * s) + hi;
            const u32 off = (ch ^ sw) << 4;
            u32 a00, a01, a02, a03, a10, a11, a12, a13;
            ldsm4(a00, a01, a02, a03, QA0 + off);
            ldsm4(a10, a11, a12, a13, QA1 + off);
            u32 b00, b01, b02, b03, b10, b11, b12, b13;
            ldsm4(b00, b01, b02, b03, B0 + off);
            ldsm4(b10, b11, b12, b13, B1 + off);
            mma_fp8(acc[0][0], a00, a01, a02, a03, b00, b02);
            mma_fp8(acc[1][0], a10, a11, a12, a13, b00, b02);
            mma_fp8(acc[0][1], a00, a01, a02, a03, b01, b03);
            mma_fp8(acc[1][1], a10, a11, a12, a13, b01, b03);
            mma_fp8(acc[0][2], a00, a01, a02, a03, b10, b12);
            mma_fp8(acc[1][2], a10, a11, a12, a13, b10, b12);
            mma_fp8(acc[0][3], a00, a01, a02, a03, b11, b13);
            mma_fp8(acc[1][3], a10, a11, a12, a13, b11, b13);
        }

        // epilogue: exp + row-side accumulate (regs) + col-side partials
        float cA[4][2] = {{0.f,0.f},{0.f,0.f},{0.f,0.f},{0.f,0.f}};
        float cP[4][2] = {{0.f,0.f},{0.f,0.f},{0.f,0.f},{0.f,0.f}};
        #pragma unroll
        for (int m = 0; m < 2; m++) {
            #pragma unroll
            for (int n = 0; n < 4; n++) {
                float e0 = ex2f(fmaf(acc[m][n][0], L2E, -L2E));
                float e1 = ex2f(fmaf(acc[m][n][1], L2E, -L2E));
                float e2 = ex2f(fmaf(acc[m][n][2], L2E, -L2E));
                float e3 = ex2f(fmaf(acc[m][n][3], L2E, -L2E));
                ra[m][0] += e0 + e1;
                ra[m][1] += e2 + e3;
                rp[m][0] = fmaf(e0, mf[n][0], fmaf(e1, mf[n][1], rp[m][0]));
                rp[m][1] = fmaf(e2, mf[n][0], fmaf(e3, mf[n][1], rp[m][1]));
                cA[n][0] += e0 + e2;
                cA[n][1] += e1 + e3;
                cP[n][0] = fmaf(e0, mc[m][0], fmaf(e2, mc[m][1], cP[n][0]));
                cP[n][1] = fmaf(e1, mc[m][0], fmaf(e3, mc[m][1], cP[n][1]));
            }
        }

        // col-side flush (off-diagonal tiles)
        if (!diag) {
            #pragma unroll
            for (int o = 4; o <= 16; o <<= 1) {
                #pragma unroll
                for (int n = 0; n < 4; n++) {
                    #pragma unroll
                    for (int bb = 0; bb < 2; bb++) {
                        cA[n][bb] += __shfl_xor_sync(0xffffffffu, cA[n][bb], o);
                        cP[n][bb] += __shfl_xor_sync(0xffffffffu, cP[n][bb], o);
                    }
                }
            }
            if (lane < 4) {
                #pragma unroll
                for (int n = 0; n < 4; n++) {
                    #pragma unroll
                    for (int bb = 0; bb < 2; bb++) {
                        int jl = cg * 32 + n * 8 + 2 * lane + bb;
                        g_tcA[nt][rg][jl] = cA[n][bb];
                        g_tcP[nt][rg][jl] = cP[n][bb];
                    }
                }
            }
        }

        // row-side flush at end of I-segment
        const bool flushNow = (t == k1 - 1) || (t == n1 - 1);
        if (flushNow) {
            #pragma unroll
            for (int o = 1; o <= 2; o <<= 1) {
                #pragma unroll
                for (int m = 0; m < 2; m++) {
                    #pragma unroll
                    for (int h = 0; h < 2; h++) {
                        ra[m][h] += __shfl_xor_sync(0xffffffffu, ra[m][h], o);
                        rp[m][h] += __shfl_xor_sync(0xffffffffu, rp[m][h], o);
                    }
                }
            }
            if (l3 == 0) {
                #pragma unroll
                for (int m = 0; m < 2; m++) {
                    #pragma unroll
                    for (int h = 0; h < 2; h++) {
                        int r = rg * 32 + m * 16 + h * 8 + lq;
                        g_rowA[I][sub][cg][r] = ra[m][h];
                        g_rowP[I][sub][cg][r] = rp[m][h];
                    }
                }
            }
            #pragma unroll
            for (int m = 0; m < 2; m++) {
                #pragma unroll
                for (int h = 0; h < 2; h++) { ra[m][h] = 0.f; rp[m][h] = 0.f; }
            }
        }
        __syncthreads();
    }
    #undef K_I
    #undef K_J

    grid_barrier();

    // ---------------- Phase 3: assemble rows + per-row loss ----------------
    if (b < NRB) {
        const int rb = b;
        const int il = tid >> 2;
        const int pp = tid & 3;
        float all = 0.f, pos = 0.f;
        #pragma unroll
        for (int c = 0; c < 4; c++) {
            all += g_rowA[rb][pp][c][il];
            pos += g_rowP[rb][pp][c][il];
        }
        for (int I2x = pp; I2x < rb; I2x += 4) {
            int n = tri(I2x) + rb - I2x;
            #pragma unroll
            for (int g = 0; g < 4; g++) {
                all += g_tcA[n][g][il];
                pos += g_tcP[n][g][il];
            }
        }
        all += __shfl_xor_sync(0xffffffffu, all, 1);
        all += __shfl_xor_sync(0xffffffffu, all, 2);
        pos += __shfl_xor_sync(0xffffffffu, pos, 1);
        pos += __shfl_xor_sync(0xffffffffu, pos, 2);
        if (pp == 0) red[il] = -logf(pos / (all + 1e-8f) + 1e-8f);
        __syncthreads();
        #pragma unroll
        for (int o = 64; o; o >>= 1) {
            if (tid < o) red[tid] += red[tid + o];
            __syncthreads();
        }
        if (tid == 0) g_partial[rb] = red[0];
    }

    grid_barrier();

    if (b == 0 && tid == 0) {
        float s = 0.f;
        #pragma unroll
        for (int i = 0; i < NRB; i++) s += g_partial[i];
        out[0] = s / (float)NROWS;
    }
}

extern "C" void kernel_launch(void* const* d_in, const int* in_sizes, int n_in,
                              void* d_out, int out_size) {
    const float* x = (const float*)d_in[0];   // [64,128,128] f32
    const int*   y = (const int*)d_in[1];     // [64] i32
    float* out = (float*)d_out;

    static int attr_set = 0;
    const int dyn_smem = 3 * TILEB;            // 48 KB
    if (!attr_set) {
        cudaFuncSetAttribute(mono_strip8_kernel,
                             cudaFuncAttributeMaxDynamicSharedMemorySize, dyn_smem);
        attr_set = 1;
    }

    mono_strip8_kernel<<<NBLK, NTHR, dyn_smem>>>(x, y, out);
}

// round 17
// speedup vs baseline: 1.1157x; 1.1157x over previous
#include <cuda_runtime.h>
#include <cuda_bf16.h>
#include <stdint.h>
#include <math.h>

typedef unsigned int u32;
typedef unsigned long long u64t;

// Fixed problem shape
#define NROWS 8192
#define DIM   128
#define BCLS  64
#define RBLK  128
#define NRB   64
#define NTILE_TOT 2080
#define NBLK  128
#define NTHR  512
#define NBUF  3
#define TILEB 32768        // bf16 tile: 128 rows x 256B

__device__ __align__(256) __nv_bfloat16 g_featb[NROWS * DIM];
__device__ float g_rowA[NRB][4][4][RBLK];     // [rowblk][sub][cg][row]
__device__ float g_rowP[NRB][4][4][RBLK];
__device__ float g_tcA[NTILE_TOT][4][RBLK];   // col-side, per rg
__device__ float g_tcP[NTILE_TOT][4][RBLK];
__device__ float g_partial[NRB];
__device__ int g_ctr;

__device__ __forceinline__ int tri(int I) { return I * 64 - ((I * (I - 1)) >> 1); }

// ---------------------------------------------------------------------------
// PTX helpers
// ---------------------------------------------------------------------------
__device__ __forceinline__ u32 smem_u32(const void* p) {
    return (u32)__cvta_generic_to_shared(p);
}
__device__ __forceinline__ void cp16(u32 dst, const void* src) {
    asm volatile("cp.async.cg.shared.global [%0], [%1], 16;\n" :: "r"(dst), "l"(src));
}
__device__ __forceinline__ void cp_mbar_arrive(u32 mbar) {
    asm volatile("cp.async.mbarrier.arrive.noinc.shared.b64 [%0];" :: "r"(mbar) : "memory");
}
__device__ __forceinline__ void mbar_init(u32 addr, u32 cnt) {
    asm volatile("mbarrier.init.shared.b64 [%0], %1;" :: "r"(addr), "r"(cnt) : "memory");
}
__device__ __forceinline__ void mbar_arrive(u32 addr) {
    asm volatile("mbarrier.arrive.shared.b64 _, [%0];" :: "r"(addr) : "memory");
}
__device__ __forceinline__ void mbar_wait(u32 addr, u32 parity) {
    asm volatile("{\n\t.reg .pred P1;\n\t"
                 "WAIT_LP_%=:\n\t"
                 "mbarrier.try_wait.parity.acquire.cta.shared::cta.b64 P1, [%0], %1, 0x989680;\n\t"
                 "@P1 bra.uni WAIT_DN_%=;\n\t"
                 "bra.uni WAIT_LP_%=;\n\t"
                 "WAIT_DN_%=:\n\t}"
                 :: "r"(addr), "r"(parity) : "memory");
}
__device__ __forceinline__ void ldsm4(u32& q0, u32& q1, u32& q2, u32& q3, u32 addr) {
    asm volatile("ldmatrix.sync.aligned.m8n8.x4.shared.b16 {%0,%1,%2,%3}, [%4];"
                 : "=r"(q0), "=r"(q1), "=r"(q2), "=r"(q3) : "r"(addr));
}
__device__ __forceinline__ void mma16816(float* dacc, u32 qa0, u32 qa1,
                                         u32 qa2, u32 qa3, u32 qb0, u32 qb1) {
    asm volatile("mma.sync.aligned.m16n8k16.row.col.f32.bf16.bf16.f32 "
                 "{%0,%1,%2,%3}, {%4,%5,%6,%7}, {%8,%9}, {%0,%1,%2,%3};"
                 : "+f"(dacc[0]), "+f"(dacc[1]), "+f"(dacc[2]), "+f"(dacc[3])
                 : "r"(qa0), "r"(qa1), "r"(qa2), "r"(qa3), "r"(qb0), "r"(qb1));
}
__device__ __forceinline__ float ex2f(float v) {
    float r;
    asm("ex2.approx.f32 %0, %1;" : "=f"(r) : "f"(v));
    return r;
}

// Re-entrant grid barrier (all NBLK blocks co-resident).
__device__ __forceinline__ void grid_barrier() {
    __syncthreads();
    if (threadIdx.x == 0) {
        __threadfence();
        int t = atomicAdd(&g_ctr, 1);
        int target = (t / NBLK + 1) * NBLK;
        while (atomicAdd(&g_ctr, 0) < target) { __nanosleep(64); }
        __threadfence();
    }
    __syncthreads();
}

// Tile loader: 128 rows x 256B -> smem, XOR-16B swizzle (512 threads, 4 each).
__device__ __forceinline__ void load_tile(u32 sbase,
                                          const __nv_bfloat16* gbase, int tid) {
    #pragma unroll
    for (int i = 0; i < 4; i++) {
        int id = i * NTHR + tid;
        int r  = id >> 4;
        int c  = id & 15;
        u32 dst = sbase + r * 256 + ((c ^ (r & 7)) << 4);
        cp16(dst, (const char*)gbase + r * 256 + c * 16);
    }
}

// ---------------------------------------------------------------------------
// ONE persistent kernel: strip-decomposed symmetric tiles, de-convoyed
// mainloop (mbarrier full/release ring, no per-tile __syncthreads).
// ---------------------------------------------------------------------------
__global__ __launch_bounds__(NTHR) void mono_async_kernel(const float* __restrict__ x,
                                                          const int* __restrict__ y,
                                                          float* __restrict__ out) {
    extern __shared__ __align__(1024) char smem[];
    __shared__ __align__(8) u64t full_sh[NBUF];
    __shared__ __align__(8) u64t rel_sh[NBUF];
    __shared__ __align__(8) u64t fullA_sh;
    __shared__ int ysm[BCLS];
    __shared__ float red[RBLK];

    const int tid  = threadIdx.x;
    const int lane = tid & 31;
    const int w    = tid >> 5;
    const int b    = blockIdx.x;

    u32 fullb[NBUF], relb[NBUF];
    #pragma unroll
    for (int i = 0; i < NBUF; i++) {
        fullb[i] = smem_u32(&full_sh[i]);
        relb[i]  = smem_u32(&rel_sh[i]);
    }
    const u32 fullA = smem_u32(&fullA_sh);
    if (tid == 0) {
        #pragma unroll
        for (int i = 0; i < NBUF; i++) { mbar_init(fullb[i], NTHR); mbar_init(relb[i], 16); }
        mbar_init(fullA, NTHR);
    }

    // ---------------- Phase 1: normalize 64 rows + zero row scratch --------
    #pragma unroll
    for (int i = 0; i < 4; i++) {
        int row = b * 64 + w * 4 + i;
        float4 v = ((const float4*)(x + (size_t)row * DIM))[lane];
        float ss = v.x * v.x + v.y * v.y + v.z * v.z + v.w * v.w;
        #pragma unroll
        for (int o = 16; o; o >>= 1) ss += __shfl_xor_sync(0xffffffffu, ss, o);
        float inv = 1.0f / fmaxf(sqrtf(ss), 1e-12f);
        __nv_bfloat162 p0 = __floats2bfloat162_rn(v.x * inv, v.y * inv);
        __nv_bfloat162 p1 = __floats2bfloat162_rn(v.z * inv, v.w * inv);
        __nv_bfloat162* dst = (__nv_bfloat162*)(g_featb + (size_t)row * DIM);
        dst[lane * 2 + 0] = p0;
        dst[lane * 2 + 1] = p1;
    }
    {   // zero g_rowA/g_rowP (131072 floats each; 1024/block/array)
        float* za = &g_rowA[0][0][0][0];
        float* zp = &g_rowP[0][0][0][0];
        za[b * 1024 + tid]       = 0.f;
        za[b * 1024 + 512 + tid] = 0.f;
        zp[b * 1024 + tid]       = 0.f;
        zp[b * 1024 + 512 + tid] = 0.f;
    }
    if (tid < BCLS) ysm[tid] = y[tid];

    grid_barrier();   // also orders mbar_init before any use

    // ---------------- Phase 2: de-convoyed strip mainloop ------------------
    const u32 sA = smem_u32(smem);
    u32 bufs[NBUF];
    #pragma unroll
    for (int i = 0; i < NBUF; i++) bufs[i] = sA + (u32)((i + 1) * TILEB);

    const int rg = w >> 2, cg = w & 3;
    const int l3 = lane & 3, lq = lane >> 2;

    const int p   = b >> 2;
    const int sub = b & 3;
    const int I2s = 63 - p;
    const int n1 = 64 - p;
    const int k0 = (sub == 0) ? 0 : sub * 16 + 1;
    const int nT = (sub == 0) ? 17 : 16;
    const int k1 = k0 + nT;

    #define K_I(k) ((k) < n1 ? p : I2s)
    #define K_J(k) ((k) < n1 ? p + (k) : I2s + ((k) - n1))

    // prologue: A + B(k0) -> buf0 (full[0]); B(k0+1) -> buf1 (full[1])
    load_tile(sA,      g_featb + (size_t)K_I(k0) * RBLK * DIM, tid);
    load_tile(bufs[0], g_featb + (size_t)K_J(k0) * RBLK * DIM, tid);
    cp_mbar_arrive(fullb[0]);
    load_tile(bufs[1], g_featb + (size_t)K_J(k0 + 1) * RBLK * DIM, tid);
    cp_mbar_arrive(fullb[1]);

    // ldsm addressing
    const u32 lr = (u32)((lane & 7) | (((lane >> 3) & 1) << 3));
    const u32 hi = (u32)(lane >> 4);
    const u32 kE = (lr & 6) << 4;
    const u32 ob = (hi ^ (lr & 1)) << 4;
    const u32 QA0 = sA + (u32)(rg * 32 + lr) * 256 + ob;
    const u32 QA1 = QA0 + 4096;
    const u32 cBo = (u32)(cg * 32 + lr) * 256 + ob;

    const float L2E = 1.4426950408889634f;
    float ra[2][2] = {{0.f,0.f},{0.f,0.f}}, rp[2][2] = {{0.f,0.f},{0.f,0.f}};

    for (int idx = 0; idx < nT; idx++) {
        const int t = k0 + idx;

        // once-per-block A reload (convoy)
        if (t == n1 && t > k0) {
            __syncthreads();   // all warps done reading old A
            load_tile(sA, g_featb + (size_t)I2s * RBLK * DIM, tid);
            cp_mbar_arrive(fullA);
            mbar_wait(fullA, 0);
        }

        // producer: load B(idx+2) into its ring slot
        const int ldt = idx + 2;
        if (ldt < nT) {
            const int bb = ldt % NBUF;
            const int uu = ldt / NBUF;
            if (uu >= 1) mbar_wait(relb[bb], (u32)((uu - 1) & 1));
            load_tile(bufs[bb], g_featb + (size_t)K_J(k0 + ldt) * RBLK * DIM, tid);
            cp_mbar_arrive(fullb[bb]);
        }

        // consumer
        const int cb = idx % NBUF;
        mbar_wait(fullb[cb], (u32)((idx / NBUF) & 1));

        const int I = K_I(t);
        const int J = K_J(t);
        const int nt = tri(I) + (J - I);
        const int clsI = ysm[I];
        const int clsJ = ysm[J];
        const bool diag = (I == J);

        float mf[4][2];
        #pragma unroll
        for (int n = 0; n < 4; n++) {
            int c0 = (cg & 1) * 32 + n * 8 + 2 * l3;
            mf[n][0] = (ysm[c0]     == clsI) ? 1.0f : 0.0f;
            mf[n][1] = (ysm[c0 + 1] == clsI) ? 1.0f : 0.0f;
        }
        float mc[2][2];
        #pragma unroll
        for (int m = 0; m < 2; m++) {
            #pragma unroll
            for (int h = 0; h < 2; h++)
                mc[m][h] = (clsJ == ysm[(rg & 1) * 32 + m * 16 + h * 8 + lq]) ? 1.0f : 0.0f;
        }

        float acc[2][4][4];
        #pragma unroll
        for (int m = 0; m < 2; m++)
            #pragma unroll
            for (int n = 0; n < 4; n++)
                #pragma unroll
                for (int q = 0; q < 4; q++) acc[m][n][q] = 0.f;

        const u32 B0 = bufs[cb] + cBo;
        const u32 B1 = B0 + 4096;

        #pragma unroll
        for (int s = 0; s < 8; s++) {
            const u32 off = ((u32)(s << 5)) ^ kE;
            u32 a00, a01, a02, a03, a10, a11, a12, a13;
            ldsm4(a00, a01, a02, a03, QA0 + off);
            ldsm4(a10, a11, a12, a13, QA1 + off);
            u32 b00, b01, b02, b03, b10, b11, b12, b13;
            ldsm4(b00, b01, b02, b03, B0 + off);
            ldsm4(b10, b11, b12, b13, B1 + off);
            mma16816(acc[0][0], a00, a01, a02, a03, b00, b02);
            mma16816(acc[1][0], a10, a11, a12, a13, b00, b02);
            mma16816(acc[0][1], a00, a01, a02, a03, b01, b03);
            mma16816(acc[1][1], a10, a11, a12, a13, b01, b03);
            mma16816(acc[0][2], a00, a01, a02, a03, b10, b12);
            mma16816(acc[1][2], a10, a11, a12, a13, b10, b12);
            mma16816(acc[0][3], a00, a01, a02, a03, b11, b13);
            mma16816(acc[1][3], a10, a11, a12, a13, b11, b13);
        }
        // this warp is done reading buffer cb
        if (lane == 0) mbar_arrive(relb[cb]);

        // epilogue (registers only)
        float cA[4][2] = {{0.f,0.f},{0.f,0.f},{0.f,0.f},{0.f,0.f}};
        float cP[4][2] = {{0.f,0.f},{0.f,0.f},{0.f,0.f},{0.f,0.f}};
        #pragma unroll
        for (int m = 0; m < 2; m++) {
            #pragma unroll
            for (int n = 0; n < 4; n++) {
                float e0 = ex2f(fmaf(acc[m][n][0], L2E, -L2E));
                float e1 = ex2f(fmaf(acc[m][n][1], L2E, -L2E));
                float e2 = ex2f(fmaf(acc[m][n][2], L2E, -L2E));
                float e3 = ex2f(fmaf(acc[m][n][3], L2E, -L2E));
                ra[m][0] += e0 + e1;
                ra[m][1] += e2 + e3;
                rp[m][0] = fmaf(e0, mf[n][0], fmaf(e1, mf[n][1], rp[m][0]));
                rp[m][1] = fmaf(e2, mf[n][0], fmaf(e3, mf[n][1], rp[m][1]));
                cA[n][0] += e0 + e2;
                cA[n][1] += e1 + e3;
                cP[n][0] = fmaf(e0, mc[m][0], fmaf(e2, mc[m][1], cP[n][0]));
                cP[n][1] = fmaf(e1, mc[m][0], fmaf(e3, mc[m][1], cP[n][1]));
            }
        }

        // col-side flush (off-diagonal)
        if (!diag) {
            #pragma unroll
            for (int o = 4; o <= 16; o <<= 1) {
                #pragma unroll
                for (int n = 0; n < 4; n++) {
                    #pragma unroll
                    for (int bb2 = 0; bb2 < 2; bb2++) {
                        cA[n][bb2] += __shfl_xor_sync(0xffffffffu, cA[n][bb2], o);
                        cP[n][bb2] += __shfl_xor_sync(0xffffffffu, cP[n][bb2], o);
                    }
                }
            }
            if (lane < 4) {
                #pragma unroll
                for (int n = 0; n < 4; n++) {
                    #pragma unroll
                    for (int bb2 = 0; bb2 < 2; bb2++) {
                        int jl = cg * 32 + n * 8 + 2 * lane + bb2;
                        g_tcA[nt][rg][jl] = cA[n][bb2];
                        g_tcP[nt][rg][jl] = cP[n][bb2];
                    }
                }
            }
        }

        // row-side flush at end of I-segment
        const bool flushNow = (t == k1 - 1) || (t == n1 - 1);
        if (flushNow) {
            #pragma unroll
            for (int o = 1; o <= 2; o <<= 1) {
                #pragma unroll
                for (int m = 0; m < 2; m++) {
                    #pragma unroll
                    for (int h = 0; h < 2; h++) {
                        ra[m][h] += __shfl_xor_sync(0xffffffffu, ra[m][h], o);
                        rp[m][h] += __shfl_xor_sync(0xffffffffu, rp[m][h], o);
                    }
                }
            }
            if (l3 == 0) {
                #pragma unroll
                for (int m = 0; m < 2; m++) {
                    #pragma unroll
                    for (int h = 0; h < 2; h++) {
                        int r = rg * 32 + m * 16 + h * 8 + lq;
                        g_rowA[I][sub][cg][r] = ra[m][h];
                        g_rowP[I][sub][cg][r] = rp[m][h];
                    }
                }
            }
            #pragma unroll
            for (int m = 0; m < 2; m++) {
                #pragma unroll
                for (int h = 0; h < 2; h++) { ra[m][h] = 0.f; rp[m][h] = 0.f; }
            }
        }
    }
    #undef K_I
    #undef K_J

    grid_barrier();

    // ---------------- Phase 3: assemble rows + per-row loss ----------------
    if (b < NRB) {
        const int rb = b;
        const int il = tid >> 2;
        const int pp = tid & 3;
        float all = 0.f, pos = 0.f;
        #pragma unroll
        for (int c = 0; c < 4; c++) {
            all += g_rowA[rb][pp][c][il];
            pos += g_rowP[rb][pp][c][il];
        }
        for (int I2x = pp; I2x < rb; I2x += 4) {
            int n = tri(I2x) + rb - I2x;
            #pragma unroll
            for (int g = 0; g < 4; g++) {
                all += g_tcA[n][g][il];
                pos += g_tcP[n][g][il];
            }
        }
        all += __shfl_xor_sync(0xffffffffu, all, 1);
        all += __shfl_xor_sync(0xffffffffu, all, 2);
        pos += __shfl_xor_sync(0xffffffffu, pos, 1);
        pos += __shfl_xor_sync(0xffffffffu, pos, 2);
        if (pp == 0) red[il] = -logf(pos / (all + 1e-8f) + 1e-8f);
        __syncthreads();
        #pragma unroll
        for (int o = 64; o; o >>= 1) {
            if (tid < o) red[tid] += red[tid + o];
            __syncthreads();
        }
        if (tid == 0) g_partial[rb] = red[0];
    }

    grid_barrier();

    if (b == 0 && tid == 0) {
        float s = 0.f;
        #pragma unroll
        for (int i = 0; i < NRB; i++) s += g_partial[i];
        out[0] = s / (float)NROWS;
    }
}

extern "C" void kernel_launch(void* const* d_in, const int* in_sizes, int n_in,
                              void* d_out, int out_size) {
    const float* x = (const float*)d_in[0];   // [64,128,128] f32
    const int*   y = (const int*)d_in[1];     // [64] i32
    float* out = (float*)d_out;

    static int attr_set = 0;
    const int dyn_smem = (1 + NBUF) * TILEB;   // 128 KB
    if (!attr_set) {
        cudaFuncSetAttribute(mono_async_kernel,
                             cudaFuncAttributeMaxDynamicSharedMemorySize, dyn_smem);
        attr_set = 1;
    }

    mono_async_kernel<<<NBLK, NTHR, dyn_smem>>>(x, y, out);
}